// round 8
// baseline (speedup 1.0000x reference)
#include <cuda_runtime.h>
#include <math.h>

#define HID   512
#define TSTEPS 8
#define LVLS  16
#define NNB   1024
#define BB    (LVLS*NNB)      /* 16384 */
#define MIDD  256
#define CONDD 256
#define EPSV  1e-5f

#define NCH1  24              /* lstm1 K=768  */
#define NCHC  16              /* cond  K=512  */
#define NCH2  26              /* lstm2 K=832  */

/* ----------------- scratch (static device, no allocs) ----------------- */
__device__ float g_h1a[(size_t)BB*HID];
__device__ float g_h1b[(size_t)BB*HID];
__device__ float g_c1 [(size_t)BB*HID];
__device__ float g_last[(size_t)BB*MIDD];
__device__ float g_h2 [NNB*HID];
__device__ float g_c2 [NNB*HID];
__device__ float g_h2i[NNB*HID];
__device__ float g_c2i[NNB*HID];
__device__ float g_part[128*2*512];
__device__ float g_ss [2*512];
/* tf32-pre-rounded inputs + packed weights */
__device__ float g_xr  [(size_t)BB*TSTEPS*CONDD];          /* 134 MB */
__device__ float g_opr [(size_t)LVLS*NNB*32];
__device__ float g_exr [(size_t)LVLS*NNB*32];
__device__ float g_wp1 [(size_t)16*NCH1*128*32];
__device__ float g_wpc [(size_t)2 *NCHC*128*32];
__device__ float g_wp2 [(size_t)16*NCH2*128*32];

/* ----------------- helpers ----------------- */
__device__ __forceinline__ float f2tf32(float x) {
    unsigned u;
    asm("cvt.rna.tf32.f32 %0, %1;" : "=r"(u) : "f"(x));
    return __uint_as_float(u);
}

__device__ __forceinline__ void mma_tf32(float* c, const float* a, const float* b) {
    asm volatile(
        "mma.sync.aligned.m16n8k8.row.col.f32.tf32.tf32.f32 "
        "{%0,%1,%2,%3}, {%4,%5,%6,%7}, {%8,%9}, {%0,%1,%2,%3};"
        : "+f"(c[0]), "+f"(c[1]), "+f"(c[2]), "+f"(c[3])
        : "r"(__float_as_uint(a[0])), "r"(__float_as_uint(a[1])),
          "r"(__float_as_uint(a[2])), "r"(__float_as_uint(a[3])),
          "r"(__float_as_uint(b[0])), "r"(__float_as_uint(b[1])));
}

__device__ __forceinline__ void cpa16(float* smem_dst, const float* gsrc) {
    unsigned s = (unsigned)__cvta_generic_to_shared(smem_dst);
    asm volatile("cp.async.cg.shared.global [%0], [%1], 16;" :: "r"(s), "l"(gsrc));
}

__device__ __forceinline__ float sigf(float x) { return 1.0f / (1.0f + expf(-x)); }

/* ----------------- prep kernels (run once per launch) ----------------- */
__global__ void round_copy(const float* __restrict__ in, float* __restrict__ out, int n)
{
    int i = blockIdx.x * 256 + threadIdx.x;
    if (i < n) out[i] = f2tf32(in[i]);
}

/* pack weights: out[((y*nCh + kc)*128 + c)*32 + kq] = tf32(W[row(c)][kc*32+kq])
   gates=1: row = y*32 + (c&31) + (c>>5)*HID ; gates=0: row = y*128 + c        */
__global__ void pack_w(const float* __restrict__ Wih, const float* __restrict__ Whh,
                       int K1, int nCh, int gates, float* __restrict__ out)
{
    int idx = blockIdx.x * 256 + threadIdx.x;
    int kq = idx & 31, c = (idx >> 5) & 127;
    int rest = idx >> 12;
    int kc = rest % nCh, y = rest / nCh;
    int k = kc * 32 + kq;
    int r = gates ? (y * 32 + (c & 31) + (c >> 5) * HID) : (y * 128 + c);
    float v = (k < K1) ? Wih[(size_t)r * K1 + k] : Whh[(size_t)r * HID + (k - K1)];
    out[idx] = f2tf32(v);
}

/* ----------------- fused cell / gemm kernel (cp.async pipelined) ----------------- */
struct CellP {
    /* A segments (k-ranges, end-exclusive; boundaries multiples of 32) */
    const float *p0, *p1, *p2, *p3;
    int e0, e1, e2;           /* k-end of segments 0..2 (seg3 = rest) */
    int s0, s1, s2, s3;       /* row stride (floats) */
    const float* bih; const float* bhh;
    const float* c_in;
    float* h_out; float* c_out;
    int K;            /* total K, multiple of 32 */
    int out_stride;   /* plain epilogue: output row stride */
};

/* GATES: 128 rows x 32 hidden units (4 gates -> 128 gate-cols), writes h,c.
   RH:    round h to tf32 at store (safe: h only consumed via mma).
   !GATES: plain 128x128 GEMM tile, bias+relu epilogue.                    */
template <bool GATES, bool RH>
__global__ void __launch_bounds__(256, 2)
mma_cell2(CellP P, const float* __restrict__ Wp)
{
    extern __shared__ float sm[];
    float* As0 = sm;           float* Bs0 = sm + 4608;
    float* As1 = sm + 9216;    float* Bs1 = sm + 13824;
    float* gs  = sm;           /* [128][132] reused after compute */
    __shared__ float bsum[128];

    const int tid = threadIdx.x;
    const int bm  = blockIdx.x;
    const int u0  = blockIdx.y * (GATES ? 32 : 128);
    const int nCh = P.K >> 5;

    if (GATES && tid < 128) {
        int r = u0 + (tid & 31) + (tid >> 5) * HID;
        bsum[tid] = P.bih[r] + P.bhh[r];
    }

    const int wm  = (tid >> 5) & 3;
    const int wn  = tid >> 7;
    const int gid = (tid & 31) >> 2;
    const int tig = tid & 3;

    float acc[2][8][4];
#pragma unroll
    for (int a = 0; a < 2; a++)
#pragma unroll
        for (int b = 0; b < 8; b++)
#pragma unroll
            for (int d = 0; d < 4; d++) acc[a][b][d] = 0.0f;

    /* ---- async tile loaders ---- */
    auto issueA = [&](int kc, float* As) {
        const int k0 = kc << 5;
        const float* ap; int ast, aks;
        if      (k0 < P.e0) { ap = P.p0; ast = P.s0; aks = 0;    }
        else if (k0 < P.e1) { ap = P.p1; ast = P.s1; aks = P.e0; }
        else if (k0 < P.e2) { ap = P.p2; ast = P.s2; aks = P.e1; }
        else                { ap = P.p3; ast = P.s3; aks = P.e2; }
#pragma unroll
        for (int i = 0; i < 4; i++) {
            int idx = i * 256 + tid;
            int row = idx >> 3, q = idx & 7;
            int k = k0 + q * 4;
            cpa16(As + row * 36 + q * 4,
                  ap + (size_t)(bm * 128 + row) * ast + (k - aks));
        }
    };
    auto issueB = [&](int kc, float* Bs) {
        const float* wb = Wp + ((size_t)(blockIdx.y * nCh + kc) << 12);
#pragma unroll
        for (int i = 0; i < 4; i++) {
            int e = i * 1024 + tid * 4;
            cpa16(Bs + (e >> 5) * 36 + (e & 31), wb + e);
        }
    };

    issueA(0, As0); issueB(0, Bs0);
    asm volatile("cp.async.commit_group;" ::: "memory");

    for (int kc = 0; kc < nCh; ++kc) {
        float* Ac = (kc & 1) ? As1 : As0;
        float* Bc = (kc & 1) ? Bs1 : Bs0;
        if (kc + 1 < nCh) {
            float* An = (kc & 1) ? As0 : As1;
            float* Bn = (kc & 1) ? Bs0 : Bs1;
            issueA(kc + 1, An); issueB(kc + 1, Bn);
            asm volatile("cp.async.commit_group;" ::: "memory");
            asm volatile("cp.async.wait_group 1;" ::: "memory");
        } else {
            asm volatile("cp.async.wait_group 0;" ::: "memory");
        }
        __syncthreads();

#pragma unroll
        for (int ks = 0; ks < 4; ks++) {
            float a[2][4], b[8][2];
            const int kk = ks * 8 + tig;
#pragma unroll
            for (int mt = 0; mt < 2; mt++) {
                int rb = wm * 32 + mt * 16 + gid;
                a[mt][0] = Ac[rb * 36 + kk];
                a[mt][1] = Ac[(rb + 8) * 36 + kk];
                a[mt][2] = Ac[rb * 36 + kk + 4];
                a[mt][3] = Ac[(rb + 8) * 36 + kk + 4];
            }
#pragma unroll
            for (int nt = 0; nt < 8; nt++) {
                int nb = wn * 64 + nt * 8 + gid;
                b[nt][0] = Bc[nb * 36 + kk];
                b[nt][1] = Bc[nb * 36 + kk + 4];
            }
#pragma unroll
            for (int mt = 0; mt < 2; mt++)
#pragma unroll
                for (int nt = 0; nt < 8; nt++)
                    mma_tf32(acc[mt][nt], a[mt], b[nt]);
        }
        __syncthreads();
    }

    if (GATES) {
#pragma unroll
        for (int mt = 0; mt < 2; mt++)
#pragma unroll
            for (int nt = 0; nt < 8; nt++) {
                int r0 = wm * 32 + mt * 16 + gid;
                int c0 = wn * 64 + nt * 8 + tig * 2;
                gs[r0 * 132 + c0]           = acc[mt][nt][0];
                gs[r0 * 132 + c0 + 1]       = acc[mt][nt][1];
                gs[(r0 + 8) * 132 + c0]     = acc[mt][nt][2];
                gs[(r0 + 8) * 132 + c0 + 1] = acc[mt][nt][3];
            }
        __syncthreads();

#pragma unroll
        for (int i = 0; i < 16; i++) {
            int cid = i * 256 + tid;
            int u = cid & 31, row = cid >> 5;
            float xi = gs[row * 132 +       u] + bsum[u];
            float xf = gs[row * 132 + 32 +  u] + bsum[32 + u];
            float xg = gs[row * 132 + 64 +  u] + bsum[64 + u];
            float xo = gs[row * 132 + 96 +  u] + bsum[96 + u];
            float iv = sigf(xi), fv = sigf(xf), ov = sigf(xo);
            float gv = tanhf(xg);
            int m  = bm * 128 + row;
            int ug = u0 + u;
            float cp = P.c_in[(size_t)m * HID + ug];
            float cn = fv * cp + iv * gv;
            float hn = ov * tanhf(cn);
            P.c_out[(size_t)m * HID + ug] = cn;
            P.h_out[(size_t)m * HID + ug] = RH ? f2tf32(hn) : hn;
        }
    } else {
#pragma unroll
        for (int mt = 0; mt < 2; mt++)
#pragma unroll
            for (int nt = 0; nt < 8; nt++) {
                int r0 = wm * 32 + mt * 16 + gid;
                int c0 = wn * 64 + nt * 8 + tig * 2;
                int m0 = bm * 128 + r0;
                int cg = u0 + c0;
                float b0 = P.bih[cg], b1 = P.bih[cg + 1];
                P.h_out[(size_t)m0 * P.out_stride + cg]           = fmaxf(acc[mt][nt][0] + b0, 0.0f);
                P.h_out[(size_t)m0 * P.out_stride + cg + 1]       = fmaxf(acc[mt][nt][1] + b1, 0.0f);
                P.h_out[(size_t)(m0 + 8) * P.out_stride + cg]     = fmaxf(acc[mt][nt][2] + b0, 0.0f);
                P.h_out[(size_t)(m0 + 8) * P.out_stride + cg + 1] = fmaxf(acc[mt][nt][3] + b1, 0.0f);
            }
    }
}

/* ----------------- tree gather (mapping is int32) ----------------- */
__global__ void gather_kernel(const int* __restrict__ mp,
                              const float* __restrict__ h, const float* __restrict__ c,
                              float* __restrict__ ho, float* __restrict__ co)
{
    int idx = blockIdx.x * blockDim.x + threadIdx.x;   /* 1024*512 */
    int n = idx >> 9, u = idx & 511;
    int m0 = mp[n * 2], m1 = mp[n * 2 + 1];
    float hv = 0.0f, cv = 0.0f;
    if (m0 > 0) { hv += h[(size_t)(m0 - 1) * HID + u]; cv += c[(size_t)(m0 - 1) * HID + u]; }
    if (m1 > 0) { hv += h[(size_t)(m1 - 1) * HID + u]; cv += c[(size_t)(m1 - 1) * HID + u]; }
    ho[idx] = f2tf32(0.5f * hv);   /* h2i feeds mma A only */
    co[idx] = 0.5f * cv;           /* cell state: full fp32 */
}

/* ----------------- deterministic batchnorm ----------------- */
__global__ void bn_partial(const float* __restrict__ x, int rows_per, float* __restrict__ part)
{
    int c = threadIdx.x; int C = blockDim.x;
    size_t r0 = (size_t)blockIdx.x * rows_per;
    float s = 0.0f, q = 0.0f;
    for (int r = 0; r < rows_per; r++) {
        float v = x[(r0 + r) * C + c];
        s += v; q += v * v;
    }
    part[(size_t)blockIdx.x * 2 * C + c]     = s;
    part[(size_t)blockIdx.x * 2 * C + C + c] = q;
}

__global__ void bn_final(const float* __restrict__ part, int nb, int rows,
                         const float* __restrict__ gamma, const float* __restrict__ beta,
                         float* __restrict__ ss)
{
    int c = threadIdx.x; int C = blockDim.x;
    float s = 0.0f, q = 0.0f;
    for (int b = 0; b < nb; b++) {
        s += part[(size_t)b * 2 * C + c];
        q += part[(size_t)b * 2 * C + C + c];
    }
    float mu  = s / rows;
    float var = q / rows - mu * mu;
    float inv = rsqrtf(var + EPSV);
    float sc  = gamma[c] * inv;
    ss[c]     = sc;
    ss[C + c] = beta[c] - mu * sc;
}

template <bool RND>
__global__ void bn_apply(const float* __restrict__ x, const float* __restrict__ ss,
                         int C, int n, float* __restrict__ out)
{
    int i = blockIdx.x * blockDim.x + threadIdx.x;
    if (i < n) {
        int c = i & (C - 1);
        float v = x[i] * ss[c] + ss[C + c];
        out[i] = RND ? f2tf32(v) : v;
    }
}

/* ----------------- host ----------------- */
extern "C" void kernel_launch(void* const* d_in, const int* in_sizes, int n_in,
                              void* d_out, int out_size)
{
    const float* operators  = (const float*)d_in[0];
    const float* extras     = (const float*)d_in[1];
    const float* conditions = (const float*)d_in[2];
    /* d_in[3] condition_masks: unused by reference */
    const int* mapping = (const int*)d_in[4];
    const float* W1ih = (const float*)d_in[5];
    const float* W1hh = (const float*)d_in[6];
    const float* b1ih = (const float*)d_in[7];
    const float* b1hh = (const float*)d_in[8];
    const float* condW = (const float*)d_in[9];
    const float* condb = (const float*)d_in[10];
    const float* bn1g = (const float*)d_in[11];
    const float* bn1b = (const float*)d_in[12];
    const float* W2ih = (const float*)d_in[13];
    const float* W2hh = (const float*)d_in[14];
    const float* b2ih = (const float*)d_in[15];
    const float* b2hh = (const float*)d_in[16];
    const float* bn2g = (const float*)d_in[17];
    const float* bn2b = (const float*)d_in[18];

    float *h1a, *h1b, *c1, *last, *h2, *c2, *h2i, *c2i, *part, *ss;
    float *xr, *opr, *exr, *wp1, *wpc, *wp2;
    cudaGetSymbolAddress((void**)&h1a,  g_h1a);
    cudaGetSymbolAddress((void**)&h1b,  g_h1b);
    cudaGetSymbolAddress((void**)&c1,   g_c1);
    cudaGetSymbolAddress((void**)&last, g_last);
    cudaGetSymbolAddress((void**)&h2,   g_h2);
    cudaGetSymbolAddress((void**)&c2,   g_c2);
    cudaGetSymbolAddress((void**)&h2i,  g_h2i);
    cudaGetSymbolAddress((void**)&c2i,  g_c2i);
    cudaGetSymbolAddress((void**)&part, g_part);
    cudaGetSymbolAddress((void**)&ss,   g_ss);
    cudaGetSymbolAddress((void**)&xr,   g_xr);
    cudaGetSymbolAddress((void**)&opr,  g_opr);
    cudaGetSymbolAddress((void**)&exr,  g_exr);
    cudaGetSymbolAddress((void**)&wp1,  g_wp1);
    cudaGetSymbolAddress((void**)&wpc,  g_wpc);
    cudaGetSymbolAddress((void**)&wp2,  g_wp2);

    const int SM_MAIN = 18432 * 4;   /* 73728 B: double-buffered tiles; epilogue fits */
    cudaFuncSetAttribute((const void*)mma_cell2<true, true>,
                         cudaFuncAttributeMaxDynamicSharedMemorySize, SM_MAIN);
    cudaFuncSetAttribute((const void*)mma_cell2<true, false>,
                         cudaFuncAttributeMaxDynamicSharedMemorySize, SM_MAIN);
    cudaFuncSetAttribute((const void*)mma_cell2<false, false>,
                         cudaFuncAttributeMaxDynamicSharedMemorySize, SM_MAIN);

    /* ---- prep: tf32-round inputs, pack+round weights ---- */
    {
        int nx = BB * TSTEPS * CONDD;
        round_copy<<<(nx + 255) / 256, 256>>>(conditions, xr, nx);
        int no = LVLS * NNB * 32;
        round_copy<<<(no + 255) / 256, 256>>>(operators, opr, no);
        round_copy<<<(no + 255) / 256, 256>>>(extras, exr, no);
        pack_w<<<16 * NCH1 * 4096 / 256, 256>>>(W1ih, W1hh, 256, NCH1, 1, wp1);
        pack_w<<<2  * NCHC * 4096 / 256, 256>>>(condW, condW, 512, NCHC, 0, wpc);
        pack_w<<<16 * NCH2 * 4096 / 256, 256>>>(W2ih, W2hh, 320, NCH2, 1, wp2);
    }

    cudaMemsetAsync(h1a, 0, (size_t)BB * HID * sizeof(float), 0);
    cudaMemsetAsync(c1,  0, (size_t)BB * HID * sizeof(float), 0);

    /* ---- lstm1: 8 fused steps, K = 256 (x_t) + 512 (h_prev) ---- */
    for (int t = 0; t < TSTEPS; t++) {
        const float* hp = (t & 1) ? h1b : h1a;
        float*       ho = (t & 1) ? h1a : h1b;
        CellP P{};
        P.p0 = xr + (size_t)t * CONDD; P.e0 = 256; P.s0 = TSTEPS * CONDD;
        P.p1 = hp; P.e1 = 768; P.s1 = HID;
        P.p2 = hp; P.e2 = 768; P.s2 = HID;
        P.p3 = hp;             P.s3 = HID;
        P.bih = b1ih; P.bhh = b1hh;
        P.c_in = c1; P.c_out = c1; P.h_out = ho;
        P.K = 768; P.out_stride = HID;
        mma_cell2<true, true><<<dim3(BB / 128, HID / 32), 256, SM_MAIN>>>(P, wp1);
    }
    const float* h1f = h1a;   /* t=7 writes h1a (tf32-rounded) */

    /* ---- cond linear + relu ---- */
    {
        CellP Q{};
        Q.p0 = h1f; Q.e0 = 512; Q.s0 = HID;
        Q.p1 = h1f; Q.e1 = 512; Q.s1 = HID;
        Q.p2 = h1f; Q.e2 = 512; Q.s2 = HID;
        Q.p3 = h1f;             Q.s3 = HID;
        Q.bih = condb; Q.bhh = condb;
        Q.c_in = nullptr; Q.c_out = nullptr; Q.h_out = last;
        Q.K = 512; Q.out_stride = MIDD;
        mma_cell2<false, false><<<dim3(BB / 128, MIDD / 128), 256, SM_MAIN>>>(Q, wpc);
    }

    /* ---- bn1 over [16384, 256]; output rounded (feeds lstm2 mma only) ---- */
    bn_partial<<<128, 256>>>(last, BB / 128, part);
    bn_final<<<1, 256>>>(part, 128, BB, bn1g, bn1b, ss);
    bn_apply<true><<<(BB * MIDD) / 256, 256>>>(last, ss, MIDD, BB * MIDD, last);

    /* ---- lstm2 tree ---- */
    cudaMemsetAsync(h2i, 0, (size_t)NNB * HID * sizeof(float), 0);
    cudaMemsetAsync(c2i, 0, (size_t)NNB * HID * sizeof(float), 0);

    for (int step = 0; step < LVLS; step++) {
        int l = LVLS - 1 - step;
        if (step > 0)
            gather_kernel<<<(NNB * HID) / 256, 256>>>(mapping + (size_t)l * NNB * 2,
                                                      h2, c2, h2i, c2i);
        CellP P{};
        P.p0 = opr + (size_t)l * NNB * 32;   P.e0 = 32;  P.s0 = 32;
        P.p1 = exr + (size_t)l * NNB * 32;   P.e1 = 64;  P.s1 = 32;
        P.p2 = last + (size_t)l * NNB * MIDD; P.e2 = 320; P.s2 = MIDD;
        P.p3 = h2i;                           P.s3 = HID;
        P.bih = b2ih; P.bhh = b2hh;
        P.c_in = c2i; P.c_out = c2; P.h_out = h2;   /* h2 stays full fp32 */
        P.K = 832; P.out_stride = HID;
        mma_cell2<true, false><<<dim3(NNB / 128, HID / 32), 256, SM_MAIN>>>(P, wp2);
    }

    /* ---- bn2 over [1024, 512] -> d_out (full precision) ---- */
    bn_partial<<<32, 512>>>(h2, NNB / 32, part);
    bn_final<<<1, 512>>>(part, 32, NNB, bn2g, bn2b, ss);
    bn_apply<false><<<(NNB * HID) / 256, 256>>>(h2, ss, HID, NNB * HID, (float*)d_out);
}

// round 13
// speedup vs baseline: 1.5298x; 1.5298x over previous
#include <cuda_runtime.h>
#include <math.h>

#define HID   512
#define TSTEPS 8
#define LVLS  16
#define NNB   1024
#define BB    (LVLS*NNB)      /* 16384 */
#define MIDD  256
#define CONDD 256
#define EPSV  1e-5f

#define NCH1  24              /* lstm1 K=768  */
#define NCHC  16              /* cond  K=512  */
#define NCH2  26              /* lstm2 K=832  */

/* ----------------- scratch (static device, no allocs) ----------------- */
__device__ float g_h1a[(size_t)BB*HID];
__device__ float g_h1b[(size_t)BB*HID];
__device__ float g_c1 [(size_t)BB*HID];
__device__ float g_last[(size_t)BB*MIDD];
__device__ float g_h2 [NNB*HID];
__device__ float g_c2 [NNB*HID];
__device__ float g_h2i[NNB*HID];
__device__ float g_c2i[NNB*HID];
__device__ float g_part[128*2*512];
__device__ float g_ss [2*512];
/* tf32-pre-rounded inputs + packed weights */
__device__ float g_xr  [(size_t)BB*TSTEPS*CONDD];
__device__ float g_opr [(size_t)LVLS*NNB*32];
__device__ float g_exr [(size_t)LVLS*NNB*32];
__device__ float g_wp1 [(size_t)16*NCH1*128*32];
__device__ float g_wpc [(size_t)2 *NCHC*128*32];
__device__ float g_wp2 [(size_t)16*NCH2*128*32];

/* ----------------- helpers ----------------- */
__device__ __forceinline__ float f2tf32(float x) {
    unsigned u;
    asm("cvt.rna.tf32.f32 %0, %1;" : "=r"(u) : "f"(x));
    return __uint_as_float(u);
}

__device__ __forceinline__ void mma_tf32(float* c, const float* a, const float* b) {
    asm volatile(
        "mma.sync.aligned.m16n8k8.row.col.f32.tf32.tf32.f32 "
        "{%0,%1,%2,%3}, {%4,%5,%6,%7}, {%8,%9}, {%0,%1,%2,%3};"
        : "+f"(c[0]), "+f"(c[1]), "+f"(c[2]), "+f"(c[3])
        : "r"(__float_as_uint(a[0])), "r"(__float_as_uint(a[1])),
          "r"(__float_as_uint(a[2])), "r"(__float_as_uint(a[3])),
          "r"(__float_as_uint(b[0])), "r"(__float_as_uint(b[1])));
}

__device__ __forceinline__ void cpa16s(unsigned sdst, const void* gsrc) {
    asm volatile("cp.async.cg.shared.global [%0], [%1], 16;" :: "r"(sdst), "l"(gsrc));
}

__device__ __forceinline__ float sigf(float x) { return 1.0f / (1.0f + expf(-x)); }

/* ----------------- prep kernels ----------------- */
__global__ void round_copy(const float* __restrict__ in, float* __restrict__ out, int n)
{
    int i = blockIdx.x * 256 + threadIdx.x;
    if (i < n) out[i] = f2tf32(in[i]);
}

/* pack weights: out[((y*nCh + kc)*128 + c)*32 + kq] = tf32(W[row(c)][kc*32+kq]) */
__global__ void pack_w(const float* __restrict__ Wih, const float* __restrict__ Whh,
                       int K1, int nCh, int gates, float* __restrict__ out)
{
    int idx = blockIdx.x * 256 + threadIdx.x;
    int kq = idx & 31, c = (idx >> 5) & 127;
    int rest = idx >> 12;
    int kc = rest % nCh, y = rest / nCh;
    int k = kc * 32 + kq;
    int r = gates ? (y * 32 + (c & 31) + (c >> 5) * HID) : (y * 128 + c);
    float v = (k < K1) ? Wih[(size_t)r * K1 + k] : Whh[(size_t)r * HID + (k - K1)];
    out[idx] = f2tf32(v);
}

/* ----------------- fused cell / gemm kernel (lean cp.async pipeline) ----------------- */
struct CellP {
    const float *p0, *p1, *p2, *p3;
    int e0, e1, e2;           /* k-end of segments 0..2 (seg3 = rest) */
    int s0, s1, s2, s3;       /* row stride (floats) */
    const float* bih; const float* bhh;
    const float* c_in;
    float* h_out; float* c_out;
    int K;                    /* total K, multiple of 32 */
    int out_stride;
};

struct ChDesc { const char* base; long strideB; };   /* 16 bytes */

template <bool GATES, bool RH>
__global__ void __launch_bounds__(256, 2)
mma_cell3(CellP P, const float* __restrict__ Wp)
{
    extern __shared__ float sm[];
    /* byte offsets inside dynamic smem: As0@0 Bs0@18432 As1@36864 Bs1@55296 */
    float* gs = sm;                       /* [128][132] reused after compute */
    __shared__ ChDesc descs[32];
    __shared__ float bsum[128];

    const int tid = threadIdx.x;
    const int bm  = blockIdx.x;
    const int u0  = blockIdx.y * (GATES ? 32 : 128);
    const int nCh = P.K >> 5;

    if (GATES && tid < 128) {
        int r = u0 + (tid & 31) + (tid >> 5) * HID;
        bsum[tid] = P.bih[r] + P.bhh[r];
    }
    /* build per-chunk A descriptors (segment logic once) */
    if (tid < nCh) {
        int k0 = tid << 5;
        const float* ap; int ast, aks;
        if      (k0 < P.e0) { ap = P.p0; ast = P.s0; aks = 0;    }
        else if (k0 < P.e1) { ap = P.p1; ast = P.s1; aks = P.e0; }
        else if (k0 < P.e2) { ap = P.p2; ast = P.s2; aks = P.e1; }
        else                { ap = P.p3; ast = P.s3; aks = P.e2; }
        descs[tid].base    = (const char*)(ap + (size_t)(bm * 128) * ast + (k0 - aks));
        descs[tid].strideB = (long)ast * 4;
    }
    __syncthreads();

    const int wm  = (tid >> 5) & 3;
    const int wn  = tid >> 7;
    const int gid = (tid & 31) >> 2;
    const int tig = tid & 3;

    /* per-thread constant offsets */
    const int r0      = tid >> 3;                       /* A/B tile row, i=0   */
    const int q16     = (tid & 7) * 16;                 /* byte offset in row  */
    unsigned  smbase  = (unsigned)__cvta_generic_to_shared(sm);
    unsigned  soff    = smbase + (unsigned)(r0 * 36 + (tid & 7) * 4) * 4;
    const char* bgp   = (const char*)(Wp + ((size_t)blockIdx.y * nCh << 12)) + tid * 16;

    float acc[2][8][4];
#pragma unroll
    for (int a = 0; a < 2; a++)
#pragma unroll
        for (int b = 0; b < 8; b++)
#pragma unroll
            for (int d = 0; d < 4; d++) acc[a][b][d] = 0.0f;

    /* prologue: chunk 0 into buffer 0 */
    {
        ChDesc d = descs[0];
        const char* ga = d.base + (long)r0 * d.strideB + q16;
        long stp = d.strideB * 32;
#pragma unroll
        for (int i = 0; i < 4; i++) {
            cpa16s(soff         + i * 4608, ga  + i * stp);
            cpa16s(soff + 18432 + i * 4608, bgp + i * 4096);
        }
        asm volatile("cp.async.commit_group;" ::: "memory");
    }

    for (int kc = 0; kc < nCh; ++kc) {
        const unsigned cbuf = (kc & 1) ? 36864u : 0u;
        if (kc + 1 < nCh) {
            const unsigned nbuf = (kc & 1) ? 0u : 36864u;
            ChDesc d = descs[kc + 1];
            const char* ga = d.base + (long)r0 * d.strideB + q16;
            long stp = d.strideB * 32;
            const char* gb = bgp + (size_t)(kc + 1) * 16384;
#pragma unroll
            for (int i = 0; i < 4; i++) {
                cpa16s(soff + nbuf         + i * 4608, ga + i * stp);
                cpa16s(soff + nbuf + 18432 + i * 4608, gb + i * 4096);
            }
            asm volatile("cp.async.commit_group;" ::: "memory");
            asm volatile("cp.async.wait_group 1;" ::: "memory");
        } else {
            asm volatile("cp.async.wait_group 0;" ::: "memory");
        }
        __syncthreads();

        const float* Ac = sm + (cbuf >> 2);
        const float* Bc = Ac + 4608;
#pragma unroll
        for (int ks = 0; ks < 4; ks++) {
            float a[2][4], b[8][2];
            const int kk = ks * 8 + tig;
#pragma unroll
            for (int mt = 0; mt < 2; mt++) {
                int rb = wm * 32 + mt * 16 + gid;
                a[mt][0] = Ac[rb * 36 + kk];
                a[mt][1] = Ac[(rb + 8) * 36 + kk];
                a[mt][2] = Ac[rb * 36 + kk + 4];
                a[mt][3] = Ac[(rb + 8) * 36 + kk + 4];
            }
#pragma unroll
            for (int nt = 0; nt < 8; nt++) {
                int nb = wn * 64 + nt * 8 + gid;
                b[nt][0] = Bc[nb * 36 + kk];
                b[nt][1] = Bc[nb * 36 + kk + 4];
            }
#pragma unroll
            for (int mt = 0; mt < 2; mt++)
#pragma unroll
                for (int nt = 0; nt < 8; nt++)
                    mma_tf32(acc[mt][nt], a[mt], b[nt]);
        }
        __syncthreads();
    }

    if (GATES) {
#pragma unroll
        for (int mt = 0; mt < 2; mt++)
#pragma unroll
            for (int nt = 0; nt < 8; nt++) {
                int rr = wm * 32 + mt * 16 + gid;
                int cc = wn * 64 + nt * 8 + tig * 2;
                gs[rr * 132 + cc]           = acc[mt][nt][0];
                gs[rr * 132 + cc + 1]       = acc[mt][nt][1];
                gs[(rr + 8) * 132 + cc]     = acc[mt][nt][2];
                gs[(rr + 8) * 132 + cc + 1] = acc[mt][nt][3];
            }
        __syncthreads();

#pragma unroll
        for (int i = 0; i < 16; i++) {
            int cid = i * 256 + tid;
            int u = cid & 31, row = cid >> 5;
            float xi = gs[row * 132 +       u] + bsum[u];
            float xf = gs[row * 132 + 32 +  u] + bsum[32 + u];
            float xg = gs[row * 132 + 64 +  u] + bsum[64 + u];
            float xo = gs[row * 132 + 96 +  u] + bsum[96 + u];
            float iv = sigf(xi), fv = sigf(xf), ov = sigf(xo);
            float gv = tanhf(xg);
            int m  = bm * 128 + row;
            int ug = u0 + u;
            float cp = P.c_in[(size_t)m * HID + ug];
            float cn = fv * cp + iv * gv;
            float hn = ov * tanhf(cn);
            P.c_out[(size_t)m * HID + ug] = cn;
            P.h_out[(size_t)m * HID + ug] = RH ? f2tf32(hn) : hn;
        }
    } else {
#pragma unroll
        for (int mt = 0; mt < 2; mt++)
#pragma unroll
            for (int nt = 0; nt < 8; nt++) {
                int rr = wm * 32 + mt * 16 + gid;
                int cc = wn * 64 + nt * 8 + tig * 2;
                int m0 = bm * 128 + rr;
                int cg = u0 + cc;
                float b0 = P.bih[cg], b1 = P.bih[cg + 1];
                P.h_out[(size_t)m0 * P.out_stride + cg]           = fmaxf(acc[mt][nt][0] + b0, 0.0f);
                P.h_out[(size_t)m0 * P.out_stride + cg + 1]       = fmaxf(acc[mt][nt][1] + b1, 0.0f);
                P.h_out[(size_t)(m0 + 8) * P.out_stride + cg]     = fmaxf(acc[mt][nt][2] + b0, 0.0f);
                P.h_out[(size_t)(m0 + 8) * P.out_stride + cg + 1] = fmaxf(acc[mt][nt][3] + b1, 0.0f);
            }
    }
}

/* ----------------- tree gather (mapping is int32) ----------------- */
__global__ void gather_kernel(const int* __restrict__ mp,
                              const float* __restrict__ h, const float* __restrict__ c,
                              float* __restrict__ ho, float* __restrict__ co)
{
    int idx = blockIdx.x * blockDim.x + threadIdx.x;
    int n = idx >> 9, u = idx & 511;
    int m0 = mp[n * 2], m1 = mp[n * 2 + 1];
    float hv = 0.0f, cv = 0.0f;
    if (m0 > 0) { hv += h[(size_t)(m0 - 1) * HID + u]; cv += c[(size_t)(m0 - 1) * HID + u]; }
    if (m1 > 0) { hv += h[(size_t)(m1 - 1) * HID + u]; cv += c[(size_t)(m1 - 1) * HID + u]; }
    ho[idx] = f2tf32(0.5f * hv);
    co[idx] = 0.5f * cv;
}

/* ----------------- deterministic batchnorm ----------------- */
__global__ void bn_partial(const float* __restrict__ x, int rows_per, float* __restrict__ part)
{
    int c = threadIdx.x; int C = blockDim.x;
    size_t r0 = (size_t)blockIdx.x * rows_per;
    float s = 0.0f, q = 0.0f;
    for (int r = 0; r < rows_per; r++) {
        float v = x[(r0 + r) * C + c];
        s += v; q += v * v;
    }
    part[(size_t)blockIdx.x * 2 * C + c]     = s;
    part[(size_t)blockIdx.x * 2 * C + C + c] = q;
}

__global__ void bn_final(const float* __restrict__ part, int nb, int rows,
                         const float* __restrict__ gamma, const float* __restrict__ beta,
                         float* __restrict__ ss)
{
    int c = threadIdx.x; int C = blockDim.x;
    float s = 0.0f, q = 0.0f;
    for (int b = 0; b < nb; b++) {
        s += part[(size_t)b * 2 * C + c];
        q += part[(size_t)b * 2 * C + C + c];
    }
    float mu  = s / rows;
    float var = q / rows - mu * mu;
    float inv = rsqrtf(var + EPSV);
    float sc  = gamma[c] * inv;
    ss[c]     = sc;
    ss[C + c] = beta[c] - mu * sc;
}

template <bool RND>
__global__ void bn_apply(const float* __restrict__ x, const float* __restrict__ ss,
                         int C, int n, float* __restrict__ out)
{
    int i = blockIdx.x * blockDim.x + threadIdx.x;
    if (i < n) {
        int c = i & (C - 1);
        float v = x[i] * ss[c] + ss[C + c];
        out[i] = RND ? f2tf32(v) : v;
    }
}

/* ----------------- host ----------------- */
extern "C" void kernel_launch(void* const* d_in, const int* in_sizes, int n_in,
                              void* d_out, int out_size)
{
    const float* operators  = (const float*)d_in[0];
    const float* extras     = (const float*)d_in[1];
    const float* conditions = (const float*)d_in[2];
    const int* mapping = (const int*)d_in[4];
    const float* W1ih = (const float*)d_in[5];
    const float* W1hh = (const float*)d_in[6];
    const float* b1ih = (const float*)d_in[7];
    const float* b1hh = (const float*)d_in[8];
    const float* condW = (const float*)d_in[9];
    const float* condb = (const float*)d_in[10];
    const float* bn1g = (const float*)d_in[11];
    const float* bn1b = (const float*)d_in[12];
    const float* W2ih = (const float*)d_in[13];
    const float* W2hh = (const float*)d_in[14];
    const float* b2ih = (const float*)d_in[15];
    const float* b2hh = (const float*)d_in[16];
    const float* bn2g = (const float*)d_in[17];
    const float* bn2b = (const float*)d_in[18];

    float *h1a, *h1b, *c1, *last, *h2, *c2, *h2i, *c2i, *part, *ss;
    float *xr, *opr, *exr, *wp1, *wpc, *wp2;
    cudaGetSymbolAddress((void**)&h1a,  g_h1a);
    cudaGetSymbolAddress((void**)&h1b,  g_h1b);
    cudaGetSymbolAddress((void**)&c1,   g_c1);
    cudaGetSymbolAddress((void**)&last, g_last);
    cudaGetSymbolAddress((void**)&h2,   g_h2);
    cudaGetSymbolAddress((void**)&c2,   g_c2);
    cudaGetSymbolAddress((void**)&h2i,  g_h2i);
    cudaGetSymbolAddress((void**)&c2i,  g_c2i);
    cudaGetSymbolAddress((void**)&part, g_part);
    cudaGetSymbolAddress((void**)&ss,   g_ss);
    cudaGetSymbolAddress((void**)&xr,   g_xr);
    cudaGetSymbolAddress((void**)&opr,  g_opr);
    cudaGetSymbolAddress((void**)&exr,  g_exr);
    cudaGetSymbolAddress((void**)&wp1,  g_wp1);
    cudaGetSymbolAddress((void**)&wpc,  g_wpc);
    cudaGetSymbolAddress((void**)&wp2,  g_wp2);

    const int SM_MAIN = 18432 * 4;   /* 73728 B dynamic */
    cudaFuncSetAttribute((const void*)mma_cell3<true, true>,
                         cudaFuncAttributeMaxDynamicSharedMemorySize, SM_MAIN);
    cudaFuncSetAttribute((const void*)mma_cell3<true, false>,
                         cudaFuncAttributeMaxDynamicSharedMemorySize, SM_MAIN);
    cudaFuncSetAttribute((const void*)mma_cell3<false, false>,
                         cudaFuncAttributeMaxDynamicSharedMemorySize, SM_MAIN);

    /* ---- prep: tf32-round inputs, pack+round weights ---- */
    {
        int nx = BB * TSTEPS * CONDD;
        round_copy<<<(nx + 255) / 256, 256>>>(conditions, xr, nx);
        int no = LVLS * NNB * 32;
        round_copy<<<(no + 255) / 256, 256>>>(operators, opr, no);
        round_copy<<<(no + 255) / 256, 256>>>(extras, exr, no);
        pack_w<<<16 * NCH1 * 4096 / 256, 256>>>(W1ih, W1hh, 256, NCH1, 1, wp1);
        pack_w<<<2  * NCHC * 4096 / 256, 256>>>(condW, condW, 512, NCHC, 0, wpc);
        pack_w<<<16 * NCH2 * 4096 / 256, 256>>>(W2ih, W2hh, 320, NCH2, 1, wp2);
    }

    cudaMemsetAsync(h1a, 0, (size_t)BB * HID * sizeof(float), 0);
    cudaMemsetAsync(c1,  0, (size_t)BB * HID * sizeof(float), 0);

    /* ---- lstm1: 8 fused steps, K = 256 (x_t) + 512 (h_prev) ---- */
    for (int t = 0; t < TSTEPS; t++) {
        const float* hp = (t & 1) ? h1b : h1a;
        float*       ho = (t & 1) ? h1a : h1b;
        CellP P{};
        P.p0 = xr + (size_t)t * CONDD; P.e0 = 256; P.s0 = TSTEPS * CONDD;
        P.p1 = hp; P.e1 = 768; P.s1 = HID;
        P.p2 = hp; P.e2 = 768; P.s2 = HID;
        P.p3 = hp;             P.s3 = HID;
        P.bih = b1ih; P.bhh = b1hh;
        P.c_in = c1; P.c_out = c1; P.h_out = ho;
        P.K = 768; P.out_stride = HID;
        mma_cell3<true, true><<<dim3(BB / 128, HID / 32), 256, SM_MAIN>>>(P, wp1);
    }
    const float* h1f = h1a;

    /* ---- cond linear + relu ---- */
    {
        CellP Q{};
        Q.p0 = h1f; Q.e0 = 512; Q.s0 = HID;
        Q.p1 = h1f; Q.e1 = 512; Q.s1 = HID;
        Q.p2 = h1f; Q.e2 = 512; Q.s2 = HID;
        Q.p3 = h1f;             Q.s3 = HID;
        Q.bih = condb; Q.bhh = condb;
        Q.c_in = nullptr; Q.c_out = nullptr; Q.h_out = last;
        Q.K = 512; Q.out_stride = MIDD;
        mma_cell3<false, false><<<dim3(BB / 128, MIDD / 128), 256, SM_MAIN>>>(Q, wpc);
    }

    /* ---- bn1 over [16384, 256]; output rounded (feeds lstm2 mma only) ---- */
    bn_partial<<<128, 256>>>(last, BB / 128, part);
    bn_final<<<1, 256>>>(part, 128, BB, bn1g, bn1b, ss);
    bn_apply<true><<<(BB * MIDD) / 256, 256>>>(last, ss, MIDD, BB * MIDD, last);

    /* ---- lstm2 tree ---- */
    cudaMemsetAsync(h2i, 0, (size_t)NNB * HID * sizeof(float), 0);
    cudaMemsetAsync(c2i, 0, (size_t)NNB * HID * sizeof(float), 0);

    for (int step = 0; step < LVLS; step++) {
        int l = LVLS - 1 - step;
        if (step > 0)
            gather_kernel<<<(NNB * HID) / 256, 256>>>(mapping + (size_t)l * NNB * 2,
                                                      h2, c2, h2i, c2i);
        CellP P{};
        P.p0 = opr + (size_t)l * NNB * 32;    P.e0 = 32;  P.s0 = 32;
        P.p1 = exr + (size_t)l * NNB * 32;    P.e1 = 64;  P.s1 = 32;
        P.p2 = last + (size_t)l * NNB * MIDD; P.e2 = 320; P.s2 = MIDD;
        P.p3 = h2i;                           P.s3 = HID;
        P.bih = b2ih; P.bhh = b2hh;
        P.c_in = c2i; P.c_out = c2; P.h_out = h2;
        P.K = 832; P.out_stride = HID;
        mma_cell3<true, false><<<dim3(NNB / 128, HID / 32), 256, SM_MAIN>>>(P, wp2);
    }

    /* ---- bn2 over [1024, 512] -> d_out ---- */
    bn_partial<<<32, 512>>>(h2, NNB / 32, part);
    bn_final<<<1, 512>>>(part, 32, NNB, bn2g, bn2b, ss);
    bn_apply<false><<<(NNB * HID) / 256, 256>>>(h2, ss, HID, NNB * HID, (float*)d_out);
}